// round 5
// baseline (speedup 1.0000x reference)
#include <cuda_runtime.h>
#include <cuda_bf16.h>

#define HDIM   64
#define NHEADS 4
#define QKDIM  256           // NHEADS * HDIM
#define N_SRC  50000
#define N_TGT  10000
#define N_E    250000
#define N_LBL  200000

#define PADK   72            // smem row stride in bf16 (144B): ldmatrix conflict-free
#define WSECT  (832 * 64)    // per (layer,edge_type) transposed weight block (elements)

// ---------------- scratch (static device memory; no allocations) ----------------
__device__ float g_xs_a[N_SRC * HDIM];
__device__ float g_xs_b[N_SRC * HDIM];
__device__ float g_xt_a[N_TGT * HDIM];
__device__ float g_xt_b[N_TGT * HDIM];

__device__ float g_q_st[N_TGT * QKDIM];
__device__ float g_k_ts[N_TGT * QKDIM];
__device__ float g_v_ts[N_TGT * QKDIM];
__device__ float g_q_ts[N_SRC * QKDIM];
__device__ float g_k_st[N_SRC * QKDIM];
__device__ float g_v_st[N_SRC * QKDIM];

// CSR (dst-sorted edges), built once per launch
__device__ int g_cnt_st[N_TGT];
__device__ int g_cnt_ts[N_SRC];
__device__ int g_rp_st[N_TGT + 1];
__device__ int g_rp_ts[N_SRC + 1];
__device__ int g_cur_st[N_TGT];
__device__ int g_cur_ts[N_SRC];
__device__ int g_csr_st[N_E];
__device__ int g_csr_ts[N_E];

// split-bf16 operands
__device__ __nv_bfloat16 g_xsh[N_SRC * HDIM];
__device__ __nv_bfloat16 g_xsl[N_SRC * HDIM];
__device__ __nv_bfloat16 g_xth[N_TGT * HDIM];
__device__ __nv_bfloat16 g_xtl[N_TGT * HDIM];
__device__ __nv_bfloat16 g_wth[4 * WSECT];   // transposed [n832][64] hi, per (l,et)
__device__ __nv_bfloat16 g_wtl[4 * WSECT];   // lo

// ---------------- helpers ----------------
__device__ __forceinline__ void split2(float v, __nv_bfloat16& h, __nv_bfloat16& l) {
    h = __float2bfloat16(v);
    l = __float2bfloat16(v - __bfloat162float(h));
}
__device__ __forceinline__ unsigned su32(const void* p) {
    unsigned a;
    asm("{ .reg .u64 t; cvta.to.shared.u64 t, %1; cvt.u32.u64 %0, t; }" : "=r"(a) : "l"(p));
    return a;
}
__device__ __forceinline__ void ldsm4(unsigned& r0, unsigned& r1, unsigned& r2, unsigned& r3,
                                      unsigned addr) {
    asm volatile("ldmatrix.sync.aligned.m8n8.x4.shared.b16 {%0,%1,%2,%3}, [%4];"
                 : "=r"(r0), "=r"(r1), "=r"(r2), "=r"(r3) : "r"(addr));
}
__device__ __forceinline__ void mma16816(float* d, const unsigned* a, unsigned b0, unsigned b1) {
    asm volatile("mma.sync.aligned.m16n8k16.row.col.f32.bf16.bf16.f32 "
                 "{%0,%1,%2,%3}, {%4,%5,%6,%7}, {%8,%9}, {%0,%1,%2,%3};"
                 : "+f"(d[0]), "+f"(d[1]), "+f"(d[2]), "+f"(d[3])
                 : "r"(a[0]), "r"(a[1]), "r"(a[2]), "r"(a[3]), "r"(b0), "r"(b1));
}

// ---------------- CSR build ----------------
__global__ void zero_cnt(int* __restrict__ a, int na, int* __restrict__ b, int nb) {
    int i = blockIdx.x * blockDim.x + threadIdx.x;
    if (i < na) a[i] = 0;
    else if (i - na < nb) b[i - na] = 0;
}

__global__ void count_kernel(const int* __restrict__ e_st, const int* __restrict__ e_ts,
                             int* __restrict__ cnt_st, int* __restrict__ cnt_ts) {
    int i = blockIdx.x * blockDim.x + threadIdx.x;
    if (i < N_E) atomicAdd(&cnt_st[e_st[N_E + i]], 1);
    else if (i < 2 * N_E) atomicAdd(&cnt_ts[e_ts[N_E + (i - N_E)]], 1);
}

// single-block exclusive scan per blockIdx (block 0: st, block 1: ts)
__global__ void scan2_kernel(const int* __restrict__ cA, int* __restrict__ rA,
                             int* __restrict__ uA, int nA,
                             const int* __restrict__ cB, int* __restrict__ rB,
                             int* __restrict__ uB, int nB) {
    const int* cnt; int* rp; int* cur; int n;
    if (blockIdx.x == 0) { cnt = cA; rp = rA; cur = uA; n = nA; }
    else                 { cnt = cB; rp = rB; cur = uB; n = nB; }
    __shared__ int ssum[1024];
    int t = threadIdx.x;
    int chunk = (n + 1023) >> 10;
    int lo = min(t * chunk, n), hi = min(lo + chunk, n);
    int s = 0;
    for (int i = lo; i < hi; i++) s += cnt[i];
    ssum[t] = s;
    __syncthreads();
    for (int d = 1; d < 1024; d <<= 1) {
        int v = (t >= d) ? ssum[t - d] : 0;
        __syncthreads();
        ssum[t] += v;
        __syncthreads();
    }
    int off = (t == 0) ? 0 : ssum[t - 1];
    for (int i = lo; i < hi; i++) { rp[i] = off; cur[i] = off; off += cnt[i]; }
    if (t == 1023) rp[n] = ssum[1023];
}

__global__ void scatter_kernel(const int* __restrict__ e_st, const int* __restrict__ e_ts,
                               int* __restrict__ cur_st, int* __restrict__ cur_ts,
                               int* __restrict__ csr_st, int* __restrict__ csr_ts) {
    int i = blockIdx.x * blockDim.x + threadIdx.x;
    if (i < N_E) {
        int s = e_st[i], d = e_st[N_E + i];
        csr_st[atomicAdd(&cur_st[d], 1)] = s;
    } else if (i < 2 * N_E) {
        int j = i - N_E;
        int s = e_ts[j], d = e_ts[N_E + j];
        csr_ts[atomicAdd(&cur_ts[d], 1)] = s;
    }
}

// ---------------- small kernels ----------------
__global__ void gather_split(const float* __restrict__ emb, const int* __restrict__ ids,
                             __nv_bfloat16* __restrict__ xh, __nv_bfloat16* __restrict__ xl,
                             int nrows) {
    int i = blockIdx.x * blockDim.x + threadIdx.x;
    if (i >= nrows * HDIM) return;
    int row = i >> 6, d = i & 63;
    float v = emb[(size_t)ids[row] * HDIM + d];
    split2(v, xh[i], xl[i]);
}

__global__ void relu_split(const float* __restrict__ x,
                           __nv_bfloat16* __restrict__ xh, __nv_bfloat16* __restrict__ xl, int n) {
    int i = blockIdx.x * blockDim.x + threadIdx.x;
    if (i >= n) return;
    float v = fmaxf(x[i], 0.0f);
    split2(v, xh[i], xl[i]);
}

// Transpose + split all weights once: wt[(le)*WSECT + n832*64 + k], n832: [Wq|Wk|Wv|Ws]
__global__ void split_w(const float* __restrict__ Wq, const float* __restrict__ Wk,
                        const float* __restrict__ Wv, const float* __restrict__ Ws,
                        __nv_bfloat16* __restrict__ wth, __nv_bfloat16* __restrict__ wtl) {
    int i = blockIdx.x * blockDim.x + threadIdx.x;
    if (i >= 4 * WSECT) return;
    int le = i / WSECT, rem = i % WSECT;
    int n = rem >> 6, k = rem & 63;
    float v;
    if (n < 256)      v = Wq[(size_t)le * 64 * 256 + k * 256 + n];
    else if (n < 512) v = Wk[(size_t)le * 64 * 256 + k * 256 + (n - 256)];
    else if (n < 768) v = Wv[(size_t)le * 64 * 256 + k * 256 + (n - 512)];
    else              v = Ws[(size_t)le * 64 * 64 + k * 64 + (n - 768)];
    split2(v, wth[i], wtl[i]);
}

// ---------------- tensor-core projection GEMM (A-resident, loops col-blocks) ----------------
__global__ void __launch_bounds__(256) proj_mma(
    const __nv_bfloat16* __restrict__ Xh, const __nv_bfloat16* __restrict__ Xl, int N,
    const __nv_bfloat16* __restrict__ Wth, const __nv_bfloat16* __restrict__ Wtl,
    int off0, int off1, int off2, int off3,
    const float* __restrict__ b0, const float* __restrict__ b1,
    const float* __restrict__ b2, const float* __restrict__ b3,
    float* __restrict__ o0, float* __restrict__ o1,
    float* __restrict__ o2, float* __restrict__ o3) {
    extern __shared__ __nv_bfloat16 sm[];
    __nv_bfloat16* Ah = sm;                    // [128][PADK]
    __nv_bfloat16* Al = Ah + 128 * PADK;
    __nv_bfloat16* Bh = Al + 128 * PADK;       // [64][PADK]
    __nv_bfloat16* Bl = Bh + 64 * PADK;

    int t = threadIdx.x;
    int rowbase = blockIdx.x * 128;

    // stage A once (hi/lo)
    const uint4* xh4 = (const uint4*)Xh;
    const uint4* xl4 = (const uint4*)Xl;
    uint4 z4 = make_uint4(0u, 0u, 0u, 0u);
    #pragma unroll
    for (int i = 0; i < 4; i++) {
        int idx = t + i * 256;
        int r = idx >> 3, c = idx & 7;
        int gr = rowbase + r;
        uint4 vh = z4, vl = z4;
        if (gr < N) { vh = xh4[(size_t)gr * 8 + c]; vl = xl4[(size_t)gr * 8 + c]; }
        *(uint4*)(Ah + r * PADK + c * 8) = vh;
        *(uint4*)(Al + r * PADK + c * 8) = vl;
    }
    __syncthreads();

    int lane = t & 31, warp = t >> 5;
    int wr = warp >> 1, wc = warp & 1;
    int lrow = lane & 7, lsel = lane >> 3;

    unsigned ah_u = su32(Ah), al_u = su32(Al), bh_u = su32(Bh), bl_u = su32(Bl);

    // hoist ALL A fragments into registers (A never changes across col-blocks)
    unsigned ah[4][2][4], al[4][2][4];
    #pragma unroll
    for (int kc = 0; kc < 4; kc++) {
        int k0 = kc * 16;
        #pragma unroll
        for (int mt = 0; mt < 2; mt++) {
            int row = wr * 32 + mt * 16 + (lsel & 1) * 8 + lrow;
            int koff = k0 + (lsel >> 1) * 8;
            unsigned boff = (unsigned)(row * PADK + koff) * 2u;
            ldsm4(ah[kc][mt][0], ah[kc][mt][1], ah[kc][mt][2], ah[kc][mt][3], ah_u + boff);
            ldsm4(al[kc][mt][0], al[kc][mt][1], al[kc][mt][2], al[kc][mt][3], al_u + boff);
        }
    }

    for (int cb = 0; cb < 13; cb++) {
        int sec = cb >> 2, lcb = cb & 3;
        int woff, ostride; const float* bias; float* out;
        if (sec == 0)      { woff = off0; bias = b0; out = o0; ostride = 256; }
        else if (sec == 1) { woff = off1; bias = b1; out = o1; ostride = 256; }
        else if (sec == 2) { woff = off2; bias = b2; out = o2; ostride = 256; }
        else               { woff = off3; bias = b3; out = o3; ostride = 64;  }
        woff += lcb * 64 * 64;

        __syncthreads();   // prior col-block's B ldsm complete before restage
        const uint4* wh4 = (const uint4*)(Wth + woff);
        const uint4* wl4 = (const uint4*)(Wtl + woff);
        #pragma unroll
        for (int i = 0; i < 2; i++) {
            int idx = t + i * 256;
            int n = idx >> 3, c = idx & 7;
            *(uint4*)(Bh + n * PADK + c * 8) = wh4[n * 8 + c];
            *(uint4*)(Bl + n * PADK + c * 8) = wl4[n * 8 + c];
        }
        __syncthreads();

        float acc[2][4][4];
        #pragma unroll
        for (int mt = 0; mt < 2; mt++)
            #pragma unroll
            for (int nt = 0; nt < 4; nt++)
                #pragma unroll
                for (int r = 0; r < 4; r++) acc[mt][nt][r] = 0.0f;

        #pragma unroll
        for (int kc = 0; kc < 4; kc++) {
            int k0 = kc * 16;
            unsigned bh[2][4], bl[2][4];
            #pragma unroll
            for (int nt2 = 0; nt2 < 2; nt2++) {
                int n = wc * 32 + nt2 * 16 + (lsel >> 1) * 8 + lrow;
                int koff = k0 + (lsel & 1) * 8;
                unsigned boff = (unsigned)(n * PADK + koff) * 2u;
                ldsm4(bh[nt2][0], bh[nt2][1], bh[nt2][2], bh[nt2][3], bh_u + boff);
                ldsm4(bl[nt2][0], bl[nt2][1], bl[nt2][2], bl[nt2][3], bl_u + boff);
            }
            #pragma unroll
            for (int mt = 0; mt < 2; mt++)
                #pragma unroll
                for (int nt = 0; nt < 4; nt++) {
                    int g = nt >> 1, hf = (nt & 1) * 2;
                    mma16816(acc[mt][nt], ah[kc][mt], bh[g][hf], bh[g][hf + 1]);
                    mma16816(acc[mt][nt], ah[kc][mt], bl[g][hf], bl[g][hf + 1]);
                    mma16816(acc[mt][nt], al[kc][mt], bh[g][hf], bh[g][hf + 1]);
                }
        }

        #pragma unroll
        for (int mt = 0; mt < 2; mt++) {
            int ra = rowbase + wr * 32 + mt * 16 + (lane >> 2);
            int rb = ra + 8;
            #pragma unroll
            for (int nt = 0; nt < 4; nt++) {
                int col = lcb * 64 + wc * 32 + nt * 8 + (lane & 3) * 2;
                float2 bv = *(const float2*)(bias + col);
                if (ra < N)
                    *(float2*)(out + (size_t)ra * ostride + col) =
                        make_float2(acc[mt][nt][0] + bv.x, acc[mt][nt][1] + bv.y);
                if (rb < N)
                    *(float2*)(out + (size_t)rb * ostride + col) =
                        make_float2(acc[mt][nt][2] + bv.x, acc[mt][nt][3] + bv.y);
            }
        }
    }
}

// ---------------- fused attention: one warp per dst, online softmax, 2-edge pipeline ----
#define UPD(i, s, vv)                                        \
    do {                                                     \
        if (s <= m##i) {                                     \
            float p = __expf(s - m##i);                      \
            d##i += p;                                       \
            a##i.x += p * vv.x; a##i.y += p * vv.y;          \
        } else {                                             \
            float sc = __expf(m##i - s);                     \
            d##i = d##i * sc + 1.0f;                         \
            a##i.x = a##i.x * sc + vv.x;                     \
            a##i.y = a##i.y * sc + vv.y;                     \
            m##i = s;                                        \
        }                                                    \
    } while (0)

#define LOADSLOT(S, idx)                                                          \
    do {                                                                          \
        int s_ = csr[idx];                                                        \
        const float4* kp_ = (const float4*)(k + (size_t)s_ * QKDIM + h * HDIM + sub * 8); \
        const float2* vp_ = (const float2*)(v + (size_t)s_ * QKDIM);              \
        S##k0 = kp_[0]; S##k1 = kp_[1];                                           \
        S##v0 = vp_[lane]; S##v1 = vp_[32 + lane];                                \
        S##v2 = vp_[64 + lane]; S##v3 = vp_[96 + lane];                           \
    } while (0)

__global__ void __launch_bounds__(128) attn_kernel(
    const int* __restrict__ rowptr, const int* __restrict__ csr,
    const float* __restrict__ q, const float* __restrict__ k,
    const float* __restrict__ v, float* __restrict__ out, int ndst) {
    int w = (blockIdx.x * blockDim.x + threadIdx.x) >> 5;
    if (w >= ndst) return;
    int lane = threadIdx.x & 31;
    int h = lane >> 3, sub = lane & 7;
    int beg = rowptr[w], end = rowptr[w + 1];
    if (beg == end) return;                       // attention adds 0; skip already stored

    const float4* qp = (const float4*)(q + (size_t)w * QKDIM + h * HDIM + sub * 8);
    float4 q0 = qp[0], q1 = qp[1];

    float m0 = -1e30f, m1 = -1e30f, m2 = -1e30f, m3 = -1e30f;
    float d0 = 0.f, d1 = 0.f, d2 = 0.f, d3 = 0.f;
    float2 a0 = {0,0}, a1 = {0,0}, a2 = {0,0}, a3 = {0,0};

    float4 Ak0, Ak1, Bk0, Bk1;
    float2 Av0, Av1, Av2, Av3, Bv0, Bv1, Bv2, Bv3;
    LOADSLOT(A, beg);
    if (beg + 1 < end) LOADSLOT(B, beg + 1);

    int e = beg;
    for (; e + 1 < end; e += 2) {
        // dots first (frees k slots), keep v copies live
        float dA = q0.x * Ak0.x + q0.y * Ak0.y + q0.z * Ak0.z + q0.w * Ak0.w
                 + q1.x * Ak1.x + q1.y * Ak1.y + q1.z * Ak1.z + q1.w * Ak1.w;
        float dB = q0.x * Bk0.x + q0.y * Bk0.y + q0.z * Bk0.z + q0.w * Bk0.w
                 + q1.x * Bk1.x + q1.y * Bk1.y + q1.z * Bk1.z + q1.w * Bk1.w;
        float2 xv0 = Av0, xv1 = Av1, xv2 = Av2, xv3 = Av3;
        float2 yv0 = Bv0, yv1 = Bv1, yv2 = Bv2, yv3 = Bv3;

        if (e + 2 < end) LOADSLOT(A, e + 2);       // prefetch next pair (MLP~4)
        if (e + 3 < end) LOADSLOT(B, e + 3);

        dA += __shfl_down_sync(0xffffffffu, dA, 4);
        dB += __shfl_down_sync(0xffffffffu, dB, 4);
        dA += __shfl_down_sync(0xffffffffu, dA, 2);
        dB += __shfl_down_sync(0xffffffffu, dB, 2);
        dA += __shfl_down_sync(0xffffffffu, dA, 1);
        dB += __shfl_down_sync(0xffffffffu, dB, 1);
        float sA0 = __shfl_sync(0xffffffffu, dA, 0)  * 0.125f;
        float sB0 = __shfl_sync(0xffffffffu, dB, 0)  * 0.125f;
        float sA1 = __shfl_sync(0xffffffffu, dA, 8)  * 0.125f;
        float sB1 = __shfl_sync(0xffffffffu, dB, 8)  * 0.125f;
        float sA2 = __shfl_sync(0xffffffffu, dA, 16) * 0.125f;
        float sB2 = __shfl_sync(0xffffffffu, dB, 16) * 0.125f;
        float sA3 = __shfl_sync(0xffffffffu, dA, 24) * 0.125f;
        float sB3 = __shfl_sync(0xffffffffu, dB, 24) * 0.125f;

        UPD(0, sA0, xv0); UPD(1, sA1, xv1); UPD(2, sA2, xv2); UPD(3, sA3, xv3);
        UPD(0, sB0, yv0); UPD(1, sB1, yv1); UPD(2, sB2, yv2); UPD(3, sB3, yv3);
    }
    if (e < end) {                                  // odd tail, data in slot A
        float dA = q0.x * Ak0.x + q0.y * Ak0.y + q0.z * Ak0.z + q0.w * Ak0.w
                 + q1.x * Ak1.x + q1.y * Ak1.y + q1.z * Ak1.z + q1.w * Ak1.w;
        dA += __shfl_down_sync(0xffffffffu, dA, 4);
        dA += __shfl_down_sync(0xffffffffu, dA, 2);
        dA += __shfl_down_sync(0xffffffffu, dA, 1);
        float sA0 = __shfl_sync(0xffffffffu, dA, 0)  * 0.125f;
        float sA1 = __shfl_sync(0xffffffffu, dA, 8)  * 0.125f;
        float sA2 = __shfl_sync(0xffffffffu, dA, 16) * 0.125f;
        float sA3 = __shfl_sync(0xffffffffu, dA, 24) * 0.125f;
        UPD(0, sA0, Av0); UPD(1, sA1, Av1); UPD(2, sA2, Av2); UPD(3, sA3, Av3);
    }

    float2* op = (float2*)(out + (size_t)w * HDIM);
    float2 cur = op[lane];
    cur.x += 0.25f * (a0.x / d0 + a1.x / d1 + a2.x / d2 + a3.x / d3);
    cur.y += 0.25f * (a0.y / d0 + a1.y / d1 + a2.y / d2 + a3.y / d3);
    op[lane] = cur;
}

// ---------------- classifier ----------------
__global__ void pred_kernel(const int* __restrict__ l0, const int* __restrict__ l1,
                            const float* __restrict__ xs, const float* __restrict__ xt,
                            float* __restrict__ out, int n) {
    int gid = blockIdx.x * blockDim.x + threadIdx.x;
    int pair = gid >> 3, sub = gid & 7;
    if (pair >= n) return;
    int a = l0[pair], b = l1[pair];
    const float4* xa = (const float4*)(xs + (size_t)a * HDIM);
    const float4* xb = (const float4*)(xt + (size_t)b * HDIM);
    float4 p0 = xa[sub * 2], p1 = xa[sub * 2 + 1];
    float4 q0 = xb[sub * 2], q1 = xb[sub * 2 + 1];
    float dot = p0.x * q0.x + p0.y * q0.y + p0.z * q0.z + p0.w * q0.w
              + p1.x * q1.x + p1.y * q1.y + p1.z * q1.z + p1.w * q1.w;
    dot += __shfl_down_sync(0xffffffffu, dot, 4, 8);
    dot += __shfl_down_sync(0xffffffffu, dot, 2, 8);
    dot += __shfl_down_sync(0xffffffffu, dot, 1, 8);
    if (sub == 0) out[pair] = dot;
}

// ---------------- launch ----------------
extern "C" void kernel_launch(void* const* d_in, const int* in_sizes, int n_in,
                              void* d_out, int out_size) {
    const float* src_emb = (const float*)d_in[0];
    const float* tgt_emb = (const float*)d_in[1];
    const float* Wq = (const float*)d_in[2];
    const float* bq = (const float*)d_in[3];
    const float* Wk = (const float*)d_in[4];
    const float* bk = (const float*)d_in[5];
    const float* Wv = (const float*)d_in[6];
    const float* bv = (const float*)d_in[7];
    const float* Ws = (const float*)d_in[8];
    const float* bs = (const float*)d_in[9];
    const int* nid_s = (const int*)d_in[10];
    const int* nid_t = (const int*)d_in[11];
    const int* e_st  = (const int*)d_in[12];
    const int* e_ts  = (const int*)d_in[13];
    const int* lbl   = (const int*)d_in[14];
    float* out = (float*)d_out;

    float *xs_a, *xs_b, *xt_a, *xt_b;
    float *q_st, *k_ts, *v_ts, *q_ts, *k_st, *v_st;
    int *cnt_st, *cnt_ts, *rp_st, *rp_ts, *cur_st, *cur_ts, *csr_st, *csr_ts;
    __nv_bfloat16 *xsh, *xsl, *xth, *xtl, *wth, *wtl;
    cudaGetSymbolAddress((void**)&xs_a, g_xs_a);
    cudaGetSymbolAddress((void**)&xs_b, g_xs_b);
    cudaGetSymbolAddress((void**)&xt_a, g_xt_a);
    cudaGetSymbolAddress((void**)&xt_b, g_xt_b);
    cudaGetSymbolAddress((void**)&q_st, g_q_st);
    cudaGetSymbolAddress((void**)&k_ts, g_k_ts);
    cudaGetSymbolAddress((void**)&v_ts, g_v_ts);
    cudaGetSymbolAddress((void**)&q_ts, g_q_ts);
    cudaGetSymbolAddress((void**)&k_st, g_k_st);
    cudaGetSymbolAddress((void**)&v_st, g_v_st);
    cudaGetSymbolAddress((void**)&cnt_st, g_cnt_st);
    cudaGetSymbolAddress((void**)&cnt_ts, g_cnt_ts);
    cudaGetSymbolAddress((void**)&rp_st, g_rp_st);
    cudaGetSymbolAddress((void**)&rp_ts, g_rp_ts);
    cudaGetSymbolAddress((void**)&cur_st, g_cur_st);
    cudaGetSymbolAddress((void**)&cur_ts, g_cur_ts);
    cudaGetSymbolAddress((void**)&csr_st, g_csr_st);
    cudaGetSymbolAddress((void**)&csr_ts, g_csr_ts);
    cudaGetSymbolAddress((void**)&xsh, g_xsh);
    cudaGetSymbolAddress((void**)&xsl, g_xsl);
    cudaGetSymbolAddress((void**)&xth, g_xth);
    cudaGetSymbolAddress((void**)&xtl, g_xtl);
    cudaGetSymbolAddress((void**)&wth, g_wth);
    cudaGetSymbolAddress((void**)&wtl, g_wtl);

    const int SMEM = (128 * PADK * 2 + 64 * PADK * 2) * 2;  // 55296 B
    cudaFuncSetAttribute(proj_mma, cudaFuncAttributeMaxDynamicSharedMemorySize, SMEM);

    // ---- CSR build (edge structure is layer-invariant) ----
    zero_cnt<<<(N_TGT + N_SRC + 255) / 256, 256>>>(cnt_st, N_TGT, cnt_ts, N_SRC);
    count_kernel<<<(2 * N_E + 255) / 256, 256>>>(e_st, e_ts, cnt_st, cnt_ts);
    scan2_kernel<<<2, 1024>>>(cnt_st, rp_st, cur_st, N_TGT, cnt_ts, rp_ts, cur_ts, N_SRC);
    scatter_kernel<<<(2 * N_E + 255) / 256, 256>>>(e_st, e_ts, cur_st, cur_ts, csr_st, csr_ts);

    gather_split<<<(N_SRC * HDIM + 255) / 256, 256>>>(src_emb, nid_s, xsh, xsl, N_SRC);
    gather_split<<<(N_TGT * HDIM + 255) / 256, 256>>>(tgt_emb, nid_t, xth, xtl, N_TGT);
    split_w<<<(4 * WSECT + 255) / 256, 256>>>(Wq, Wk, Wv, Ws, wth, wtl);

    for (int l = 0; l < 2; l++) {
        float* out_s = l ? xs_a : xs_b;
        float* out_t = l ? xt_a : xt_b;
        if (l) {
            relu_split<<<(N_SRC * HDIM + 255) / 256, 256>>>(xs_b, xsh, xsl, N_SRC * HDIM);
            relu_split<<<(N_TGT * HDIM + 255) / 256, 256>>>(xt_b, xth, xtl, N_TGT * HDIM);
        }

        int le0 = l * 2 + 0, le1 = l * 2 + 1;
        // src-side: k_st(Wk l,0), v_st(Wv l,0), q_ts(Wq l,1), skip(Ws l,1)
        proj_mma<<<(N_SRC + 127) / 128, 256, SMEM>>>(xsh, xsl, N_SRC, wth, wtl,
            le0 * WSECT + 256 * 64, le0 * WSECT + 512 * 64,
            le1 * WSECT + 0,        le1 * WSECT + 768 * 64,
            bk + le0 * 256, bv + le0 * 256, bq + le1 * 256, bs + le1 * 64,
            k_st, v_st, q_ts, out_s);
        // tgt-side: q_st(Wq l,0), k_ts(Wk l,1), v_ts(Wv l,1), skip(Ws l,0)
        proj_mma<<<(N_TGT + 127) / 128, 256, SMEM>>>(xth, xtl, N_TGT, wth, wtl,
            le0 * WSECT + 0,        le1 * WSECT + 256 * 64,
            le1 * WSECT + 512 * 64, le0 * WSECT + 768 * 64,
            bq + le0 * 256, bk + le1 * 256, bv + le1 * 256, bs + le0 * 64,
            q_st, k_ts, v_ts, out_t);

        // fused attention (adds onto skip in out_t / out_s)
        attn_kernel<<<(N_TGT * 32 + 127) / 128, 128>>>(rp_st, csr_st, q_st, k_st, v_st,
                                                       out_t, N_TGT);
        attn_kernel<<<(N_SRC * 32 + 127) / 128, 128>>>(rp_ts, csr_ts, q_ts, k_ts, v_ts,
                                                       out_s, N_SRC);
    }

    pred_kernel<<<(N_LBL * 8 + 255) / 256, 256>>>(lbl, lbl + N_LBL, xs_a, xt_a, out, N_LBL);
}

// round 6
// speedup vs baseline: 1.1397x; 1.1397x over previous
#include <cuda_runtime.h>
#include <cuda_bf16.h>

#define HDIM   64
#define NHEADS 4
#define QKDIM  256           // NHEADS * HDIM
#define N_SRC  50000
#define N_TGT  10000
#define N_E    250000
#define N_LBL  200000

#define PADK   72            // smem row stride in bf16 (144B): ldmatrix conflict-free
#define WSECT  (832 * 64)    // per (layer,edge_type) transposed weight block (elements)

// ---------------- scratch (static device memory; no allocations) ----------------
__device__ float g_xs_a[N_SRC * HDIM];
__device__ float g_xs_b[N_SRC * HDIM];
__device__ float g_xt_a[N_TGT * HDIM];
__device__ float g_xt_b[N_TGT * HDIM];

__device__ float g_q_st[N_TGT * QKDIM];
__device__ float g_k_ts[N_TGT * QKDIM];
__device__ float g_v_ts[N_TGT * QKDIM];
__device__ float g_q_ts[N_SRC * QKDIM];
__device__ float g_k_st[N_SRC * QKDIM];
__device__ float g_v_st[N_SRC * QKDIM];

__device__ float g_sc_st[N_E * NHEADS];
__device__ float g_sc_ts[N_E * NHEADS];
__device__ float g_d_st[N_TGT * NHEADS];
__device__ float g_d_ts[N_SRC * NHEADS];

// split-bf16 operands
__device__ __nv_bfloat16 g_xsh[N_SRC * HDIM];
__device__ __nv_bfloat16 g_xsl[N_SRC * HDIM];
__device__ __nv_bfloat16 g_xth[N_TGT * HDIM];
__device__ __nv_bfloat16 g_xtl[N_TGT * HDIM];
__device__ __nv_bfloat16 g_wth[4 * WSECT];   // transposed [n832][64] hi, per (l,et)
__device__ __nv_bfloat16 g_wtl[4 * WSECT];   // lo

// ---------------- helpers ----------------
__device__ __forceinline__ void split2(float v, __nv_bfloat16& h, __nv_bfloat16& l) {
    h = __float2bfloat16(v);
    l = __float2bfloat16(v - __bfloat162float(h));
}
__device__ __forceinline__ unsigned su32(const void* p) {
    unsigned a;
    asm("{ .reg .u64 t; cvta.to.shared.u64 t, %1; cvt.u32.u64 %0, t; }" : "=r"(a) : "l"(p));
    return a;
}
__device__ __forceinline__ void ldsm4(unsigned& r0, unsigned& r1, unsigned& r2, unsigned& r3,
                                      unsigned addr) {
    asm volatile("ldmatrix.sync.aligned.m8n8.x4.shared.b16 {%0,%1,%2,%3}, [%4];"
                 : "=r"(r0), "=r"(r1), "=r"(r2), "=r"(r3) : "r"(addr));
}
__device__ __forceinline__ void mma16816(float* d, const unsigned* a, unsigned b0, unsigned b1) {
    asm volatile("mma.sync.aligned.m16n8k16.row.col.f32.bf16.bf16.f32 "
                 "{%0,%1,%2,%3}, {%4,%5,%6,%7}, {%8,%9}, {%0,%1,%2,%3};"
                 : "+f"(d[0]), "+f"(d[1]), "+f"(d[2]), "+f"(d[3])
                 : "r"(a[0]), "r"(a[1]), "r"(a[2]), "r"(a[3]), "r"(b0), "r"(b1));
}

// ---------------- small kernels ----------------
__global__ void zero2_kernel(float* __restrict__ a, int na, float* __restrict__ b, int nb) {
    int i = blockIdx.x * blockDim.x + threadIdx.x;
    if (i < na) { a[i] = 0.0f; return; }
    i -= na;
    if (i < nb) b[i] = 0.0f;
}

__global__ void gather_split(const float* __restrict__ emb, const int* __restrict__ ids,
                             __nv_bfloat16* __restrict__ xh, __nv_bfloat16* __restrict__ xl,
                             int nrows) {
    int i = blockIdx.x * blockDim.x + threadIdx.x;
    if (i >= nrows * HDIM) return;
    int row = i >> 6, d = i & 63;
    float v = emb[(size_t)ids[row] * HDIM + d];
    split2(v, xh[i], xl[i]);
}

__global__ void relu_split(const float* __restrict__ x,
                           __nv_bfloat16* __restrict__ xh, __nv_bfloat16* __restrict__ xl, int n) {
    int i = blockIdx.x * blockDim.x + threadIdx.x;
    if (i >= n) return;
    float v = fmaxf(x[i], 0.0f);
    split2(v, xh[i], xl[i]);
}

// Transpose + split all weights once: wt[(le)*WSECT + n832*64 + k], n832: [Wq|Wk|Wv|Ws]
__global__ void split_w(const float* __restrict__ Wq, const float* __restrict__ Wk,
                        const float* __restrict__ Wv, const float* __restrict__ Ws,
                        __nv_bfloat16* __restrict__ wth, __nv_bfloat16* __restrict__ wtl) {
    int i = blockIdx.x * blockDim.x + threadIdx.x;
    if (i >= 4 * WSECT) return;
    int le = i / WSECT, rem = i % WSECT;
    int n = rem >> 6, k = rem & 63;
    float v;
    if (n < 256)      v = Wq[(size_t)le * 64 * 256 + k * 256 + n];
    else if (n < 512) v = Wk[(size_t)le * 64 * 256 + k * 256 + (n - 256)];
    else if (n < 768) v = Wv[(size_t)le * 64 * 256 + k * 256 + (n - 512)];
    else              v = Ws[(size_t)le * 64 * 64 + k * 64 + (n - 768)];
    split2(v, wth[i], wtl[i]);
}

// ---------------- tensor-core projection GEMM (exact R3 version, proven 180us) ------
__global__ void __launch_bounds__(256) proj_mma(
    const __nv_bfloat16* __restrict__ Xh, const __nv_bfloat16* __restrict__ Xl, int N,
    const __nv_bfloat16* __restrict__ Wth, const __nv_bfloat16* __restrict__ Wtl,
    int off0, int off1, int off2, int off3,
    const float* __restrict__ b0, const float* __restrict__ b1,
    const float* __restrict__ b2, const float* __restrict__ b3,
    float* __restrict__ o0, float* __restrict__ o1,
    float* __restrict__ o2, float* __restrict__ o3) {
    extern __shared__ __nv_bfloat16 sm[];
    __nv_bfloat16* Ah = sm;                    // [128][PADK]
    __nv_bfloat16* Al = Ah + 128 * PADK;
    __nv_bfloat16* Bh = Al + 128 * PADK;       // [64][PADK]
    __nv_bfloat16* Bl = Bh + 64 * PADK;

    int cb = blockIdx.y;                       // 0..12
    int sec = cb >> 2, lcb = cb & 3;
    int woff, ostride; const float* bias; float* out;
    if (sec == 0)      { woff = off0; bias = b0; out = o0; ostride = 256; }
    else if (sec == 1) { woff = off1; bias = b1; out = o1; ostride = 256; }
    else if (sec == 2) { woff = off2; bias = b2; out = o2; ostride = 256; }
    else               { woff = off3; bias = b3; out = o3; ostride = 64;  }
    woff += lcb * 64 * 64;

    int t = threadIdx.x;
    int rowbase = blockIdx.x * 128;

    const uint4* xh4 = (const uint4*)Xh;
    const uint4* xl4 = (const uint4*)Xl;
    uint4 z4 = make_uint4(0u, 0u, 0u, 0u);
    #pragma unroll
    for (int i = 0; i < 4; i++) {
        int idx = t + i * 256;
        int r = idx >> 3, c = idx & 7;
        int gr = rowbase + r;
        uint4 vh = z4, vl = z4;
        if (gr < N) { vh = xh4[(size_t)gr * 8 + c]; vl = xl4[(size_t)gr * 8 + c]; }
        *(uint4*)(Ah + r * PADK + c * 8) = vh;
        *(uint4*)(Al + r * PADK + c * 8) = vl;
    }
    const uint4* wh4 = (const uint4*)(Wth + woff);
    const uint4* wl4 = (const uint4*)(Wtl + woff);
    #pragma unroll
    for (int i = 0; i < 2; i++) {
        int idx = t + i * 256;
        int n = idx >> 3, c = idx & 7;
        *(uint4*)(Bh + n * PADK + c * 8) = wh4[n * 8 + c];
        *(uint4*)(Bl + n * PADK + c * 8) = wl4[n * 8 + c];
    }
    __syncthreads();

    int lane = t & 31, warp = t >> 5;
    int wr = warp >> 1, wc = warp & 1;
    int lrow = lane & 7, lsel = lane >> 3;

    float acc[2][4][4];
    #pragma unroll
    for (int mt = 0; mt < 2; mt++)
        #pragma unroll
        for (int nt = 0; nt < 4; nt++)
            #pragma unroll
            for (int r = 0; r < 4; r++) acc[mt][nt][r] = 0.0f;

    unsigned ah_u = su32(Ah), al_u = su32(Al), bh_u = su32(Bh), bl_u = su32(Bl);

    #pragma unroll
    for (int kc = 0; kc < 4; kc++) {
        int k0 = kc * 16;
        unsigned ah[2][4], al[2][4], bh[2][4], bl[2][4];
        #pragma unroll
        for (int mt = 0; mt < 2; mt++) {
            int row = wr * 32 + mt * 16 + (lsel & 1) * 8 + lrow;
            int koff = k0 + (lsel >> 1) * 8;
            unsigned boff = (unsigned)(row * PADK + koff) * 2u;
            ldsm4(ah[mt][0], ah[mt][1], ah[mt][2], ah[mt][3], ah_u + boff);
            ldsm4(al[mt][0], al[mt][1], al[mt][2], al[mt][3], al_u + boff);
        }
        #pragma unroll
        for (int nt2 = 0; nt2 < 2; nt2++) {
            int n = wc * 32 + nt2 * 16 + (lsel >> 1) * 8 + lrow;
            int koff = k0 + (lsel & 1) * 8;
            unsigned boff = (unsigned)(n * PADK + koff) * 2u;
            ldsm4(bh[nt2][0], bh[nt2][1], bh[nt2][2], bh[nt2][3], bh_u + boff);
            ldsm4(bl[nt2][0], bl[nt2][1], bl[nt2][2], bl[nt2][3], bl_u + boff);
        }
        #pragma unroll
        for (int mt = 0; mt < 2; mt++)
            #pragma unroll
            for (int nt = 0; nt < 4; nt++) {
                int g = nt >> 1, hf = (nt & 1) * 2;
                mma16816(acc[mt][nt], ah[mt], bh[g][hf], bh[g][hf + 1]);
                mma16816(acc[mt][nt], ah[mt], bl[g][hf], bl[g][hf + 1]);
                mma16816(acc[mt][nt], al[mt], bh[g][hf], bh[g][hf + 1]);
            }
    }

    #pragma unroll
    for (int mt = 0; mt < 2; mt++) {
        int ra = rowbase + wr * 32 + mt * 16 + (lane >> 2);
        int rb = ra + 8;
        #pragma unroll
        for (int nt = 0; nt < 4; nt++) {
            int col = lcb * 64 + wc * 32 + nt * 8 + (lane & 3) * 2;
            float2 bv = *(const float2*)(bias + col);
            if (ra < N)
                *(float2*)(out + (size_t)ra * ostride + col) =
                    make_float2(acc[mt][nt][0] + bv.x, acc[mt][nt][1] + bv.y);
            if (rb < N)
                *(float2*)(out + (size_t)rb * ostride + col) =
                    make_float2(acc[mt][nt][2] + bv.x, acc[mt][nt][3] + bv.y);
        }
    }
}

// ---------------- fused score+exp+denom pass (softmax without max-shift) ----------------
// One warp per edge; 8 lanes per head. exp(s) is safe: |s| <~ 20 in fp32.
__global__ void scoreexp_kernel(const int* __restrict__ esrc, const int* __restrict__ edst,
                                const float* __restrict__ q, const float* __restrict__ k,
                                float* __restrict__ score, float* __restrict__ denom,
                                int nedge) {
    int warp = (blockIdx.x * blockDim.x + threadIdx.x) >> 5;
    if (warp >= nedge) return;
    int lane = threadIdx.x & 31;
    int s = esrc[warp], d = edst[warp];
    int h = lane >> 3, sub = lane & 7;
    const float4* qp = (const float4*)(q + (size_t)d * QKDIM + h * HDIM + sub * 8);
    const float4* kp = (const float4*)(k + (size_t)s * QKDIM + h * HDIM + sub * 8);
    float4 q0 = qp[0], q1 = qp[1];
    float4 k0 = kp[0], k1 = kp[1];
    float dot = q0.x * k0.x + q0.y * k0.y + q0.z * k0.z + q0.w * k0.w
              + q1.x * k1.x + q1.y * k1.y + q1.z * k1.z + q1.w * k1.w;
    dot += __shfl_down_sync(0xffffffffu, dot, 4, 8);
    dot += __shfl_down_sync(0xffffffffu, dot, 2, 8);
    dot += __shfl_down_sync(0xffffffffu, dot, 1, 8);
    if (sub == 0) {
        float ex = __expf(dot * 0.125f);
        score[(size_t)warp * NHEADS + h] = ex;
        atomicAdd(&denom[(size_t)d * NHEADS + h], ex);
    }
}

// ---------------- aggregation pass (proven) ----------------
__global__ void agg_kernel(const int* __restrict__ esrc, const int* __restrict__ edst,
                           const float* __restrict__ sc, const float* __restrict__ den,
                           const float* __restrict__ v, float* __restrict__ out, int nedge) {
    int warp = (blockIdx.x * blockDim.x + threadIdx.x) >> 5;
    if (warp >= nedge) return;
    int lane = threadIdx.x & 31;
    int s = esrc[warp], d = edst[warp];
    size_t eb = (size_t)warp * NHEADS, db = (size_t)d * NHEADS;
    float a0 = sc[eb + 0] / den[db + 0];
    float a1 = sc[eb + 1] / den[db + 1];
    float a2 = sc[eb + 2] / den[db + 2];
    float a3 = sc[eb + 3] / den[db + 3];
    const float2* vp = (const float2*)(v + (size_t)s * QKDIM);
    float2 v0 = vp[lane], v1 = vp[32 + lane], v2 = vp[64 + lane], v3 = vp[96 + lane];
    float ax = 0.25f * (a0 * v0.x + a1 * v1.x + a2 * v2.x + a3 * v3.x);
    float ay = 0.25f * (a0 * v0.y + a1 * v1.y + a2 * v2.y + a3 * v3.y);
    atomicAdd(&out[(size_t)d * HDIM + lane * 2 + 0], ax);
    atomicAdd(&out[(size_t)d * HDIM + lane * 2 + 1], ay);
}

// ---------------- classifier ----------------
__global__ void pred_kernel(const int* __restrict__ l0, const int* __restrict__ l1,
                            const float* __restrict__ xs, const float* __restrict__ xt,
                            float* __restrict__ out, int n) {
    int gid = blockIdx.x * blockDim.x + threadIdx.x;
    int pair = gid >> 3, sub = gid & 7;
    if (pair >= n) return;
    int a = l0[pair], b = l1[pair];
    const float4* xa = (const float4*)(xs + (size_t)a * HDIM);
    const float4* xb = (const float4*)(xt + (size_t)b * HDIM);
    float4 p0 = xa[sub * 2], p1 = xa[sub * 2 + 1];
    float4 q0 = xb[sub * 2], q1 = xb[sub * 2 + 1];
    float dot = p0.x * q0.x + p0.y * q0.y + p0.z * q0.z + p0.w * q0.w
              + p1.x * q1.x + p1.y * q1.y + p1.z * q1.z + p1.w * q1.w;
    dot += __shfl_down_sync(0xffffffffu, dot, 4, 8);
    dot += __shfl_down_sync(0xffffffffu, dot, 2, 8);
    dot += __shfl_down_sync(0xffffffffu, dot, 1, 8);
    if (sub == 0) out[pair] = dot;
}

// ---------------- launch ----------------
extern "C" void kernel_launch(void* const* d_in, const int* in_sizes, int n_in,
                              void* d_out, int out_size) {
    const float* src_emb = (const float*)d_in[0];
    const float* tgt_emb = (const float*)d_in[1];
    const float* Wq = (const float*)d_in[2];
    const float* bq = (const float*)d_in[3];
    const float* Wk = (const float*)d_in[4];
    const float* bk = (const float*)d_in[5];
    const float* Wv = (const float*)d_in[6];
    const float* bv = (const float*)d_in[7];
    const float* Ws = (const float*)d_in[8];
    const float* bs = (const float*)d_in[9];
    const int* nid_s = (const int*)d_in[10];
    const int* nid_t = (const int*)d_in[11];
    const int* e_st  = (const int*)d_in[12];
    const int* e_ts  = (const int*)d_in[13];
    const int* lbl   = (const int*)d_in[14];
    float* out = (float*)d_out;

    float *xs_a, *xs_b, *xt_a, *xt_b;
    float *q_st, *k_ts, *v_ts, *q_ts, *k_st, *v_st;
    float *sc_st, *sc_ts, *d_st, *d_ts;
    __nv_bfloat16 *xsh, *xsl, *xth, *xtl, *wth, *wtl;
    cudaGetSymbolAddress((void**)&xs_a, g_xs_a);
    cudaGetSymbolAddress((void**)&xs_b, g_xs_b);
    cudaGetSymbolAddress((void**)&xt_a, g_xt_a);
    cudaGetSymbolAddress((void**)&xt_b, g_xt_b);
    cudaGetSymbolAddress((void**)&q_st, g_q_st);
    cudaGetSymbolAddress((void**)&k_ts, g_k_ts);
    cudaGetSymbolAddress((void**)&v_ts, g_v_ts);
    cudaGetSymbolAddress((void**)&q_ts, g_q_ts);
    cudaGetSymbolAddress((void**)&k_st, g_k_st);
    cudaGetSymbolAddress((void**)&v_st, g_v_st);
    cudaGetSymbolAddress((void**)&sc_st, g_sc_st);
    cudaGetSymbolAddress((void**)&sc_ts, g_sc_ts);
    cudaGetSymbolAddress((void**)&d_st, g_d_st);
    cudaGetSymbolAddress((void**)&d_ts, g_d_ts);
    cudaGetSymbolAddress((void**)&xsh, g_xsh);
    cudaGetSymbolAddress((void**)&xsl, g_xsl);
    cudaGetSymbolAddress((void**)&xth, g_xth);
    cudaGetSymbolAddress((void**)&xtl, g_xtl);
    cudaGetSymbolAddress((void**)&wth, g_wth);
    cudaGetSymbolAddress((void**)&wtl, g_wtl);

    const int SMEM = (128 * PADK * 2 + 64 * PADK * 2) * 2;  // 55296 B
    cudaFuncSetAttribute(proj_mma, cudaFuncAttributeMaxDynamicSharedMemorySize, SMEM);

    gather_split<<<(N_SRC * HDIM + 255) / 256, 256>>>(src_emb, nid_s, xsh, xsl, N_SRC);
    gather_split<<<(N_TGT * HDIM + 255) / 256, 256>>>(tgt_emb, nid_t, xth, xtl, N_TGT);
    split_w<<<(4 * WSECT + 255) / 256, 256>>>(Wq, Wk, Wv, Ws, wth, wtl);

    for (int l = 0; l < 2; l++) {
        float* out_s = l ? xs_a : xs_b;
        float* out_t = l ? xt_a : xt_b;
        if (l) {
            relu_split<<<(N_SRC * HDIM + 255) / 256, 256>>>(xs_b, xsh, xsl, N_SRC * HDIM);
            relu_split<<<(N_TGT * HDIM + 255) / 256, 256>>>(xt_b, xth, xtl, N_TGT * HDIM);
        }

        int nz = (N_TGT + N_SRC) * NHEADS;
        zero2_kernel<<<(nz + 255) / 256, 256>>>(d_st, N_TGT * NHEADS, d_ts, N_SRC * NHEADS);

        int le0 = l * 2 + 0, le1 = l * 2 + 1;
        dim3 gs((N_SRC + 127) / 128, 13), gt((N_TGT + 127) / 128, 13);
        // src-side: k_st(Wk l,0), v_st(Wv l,0), q_ts(Wq l,1), skip(Ws l,1)
        proj_mma<<<gs, 256, SMEM>>>(xsh, xsl, N_SRC, wth, wtl,
            le0 * WSECT + 256 * 64, le0 * WSECT + 512 * 64,
            le1 * WSECT + 0,        le1 * WSECT + 768 * 64,
            bk + le0 * 256, bv + le0 * 256, bq + le1 * 256, bs + le1 * 64,
            k_st, v_st, q_ts, out_s);
        // tgt-side: q_st(Wq l,0), k_ts(Wk l,1), v_ts(Wv l,1), skip(Ws l,0)
        proj_mma<<<gt, 256, SMEM>>>(xth, xtl, N_TGT, wth, wtl,
            le0 * WSECT + 0,        le1 * WSECT + 256 * 64,
            le1 * WSECT + 512 * 64, le0 * WSECT + 768 * 64,
            bq + le0 * 256, bk + le1 * 256, bv + le1 * 256, bs + le0 * 64,
            q_st, k_ts, v_ts, out_t);

        int sb = (N_E * 32 + 255) / 256;  // one warp per edge
        scoreexp_kernel<<<sb, 256>>>(e_st, e_st + N_E, q_st, k_st, sc_st, d_st, N_E);
        scoreexp_kernel<<<sb, 256>>>(e_ts, e_ts + N_E, q_ts, k_ts, sc_ts, d_ts, N_E);

        agg_kernel<<<sb, 256>>>(e_st, e_st + N_E, sc_st, d_st, v_st, out_t, N_E);
        agg_kernel<<<sb, 256>>>(e_ts, e_ts + N_E, sc_ts, d_ts, v_ts, out_s, N_E);
    }

    pred_kernel<<<(N_LBL * 8 + 255) / 256, 256>>>(lbl, lbl + N_LBL, xs_a, xt_a, out, N_LBL);
}